// round 8
// baseline (speedup 1.0000x reference)
#include <cuda_runtime.h>
#include <cuda_bf16.h>
#include <math.h>

#define N_NODES 25000
#define N_EDGES 400000
#define HID 64
#define EMB 8
#define N_GRAPHS 16
#define N_CLASSES 10
#define KDIM 512     /* EMB*HID */
#define TM 32        /* node tile per block in fused layer kernel */
#define ASTRIDE 516  /* smem A row stride (mod 32 == 4 -> conflict-free frags) */
#define WSTRIDE 72   /* smem W row stride (mod 32 == 8 -> conflict-free frags) */
#define LAYER_THREADS 512
#define LAYER_SMEM ((TM * ASTRIDE + 32 * WSTRIDE) * 4)
#define BN_EPS 1e-5f
#define INV_N (1.0f / (float)N_NODES)

// ---------------- scratch (device globals; no allocation allowed) ----------
__device__ float g_R0[N_NODES * HID];
__device__ float g_R1[N_NODES * HID];
__device__ float g_R2[N_NODES * HID];
__device__ float g_D[(size_t)N_EDGES * EMB];      // directions in ORIGINAL edge order
__device__ int2  g_se[N_EDGES];                   // CSR-ordered {src, edge_id}
__device__ int   g_rowptr[N_NODES + 1];
__device__ int   g_cnt[N_NODES];
__device__ int   g_cur[N_NODES];
__device__ float g_sumsL[3 * HID];
__device__ float g_sumsqL[3 * HID];
__device__ float g_poolR[3 * N_GRAPHS * HID];     // per-layer per-graph sums of relu(agg)
__device__ float g_gcntf[N_GRAPHS];               // nodes per graph (as float)

// ---------------- tf32 helpers ---------------------------------------------
__device__ __forceinline__ unsigned tf32cvt(float x) {
    unsigned r;
    asm("cvt.rna.tf32.f32 %0, %1;" : "=r"(r) : "f"(x));
    return r;
}
__device__ __forceinline__ void mma_tf32(float* c,
                                         unsigned a0, unsigned a1, unsigned a2, unsigned a3,
                                         unsigned b0, unsigned b1) {
    asm volatile(
        "mma.sync.aligned.m16n8k8.row.col.f32.tf32.tf32.f32 "
        "{%0,%1,%2,%3}, {%4,%5,%6,%7}, {%8,%9}, {%0,%1,%2,%3};"
        : "+f"(c[0]), "+f"(c[1]), "+f"(c[2]), "+f"(c[3])
        : "r"(a0), "r"(a1), "r"(a2), "r"(a3), "r"(b0), "r"(b1));
}

// ---------------- CSR build + state reset ----------------------------------
__global__ void k_zero_cc() {
    int i = blockIdx.x * blockDim.x + threadIdx.x;
    if (i < N_NODES) { g_cnt[i] = 0; g_cur[i] = 0; }
    if (blockIdx.x == 0) {
        int t = threadIdx.x;
        for (int j = t; j < 3 * HID; j += blockDim.x) { g_sumsL[j] = 0.f; g_sumsqL[j] = 0.f; }
        for (int j = t; j < 3 * N_GRAPHS * HID; j += blockDim.x) g_poolR[j] = 0.f;
    }
}

// histogram of dst + per-edge normalized direction (coalesced write, edge order)
__global__ void k_hist_dir(const int* __restrict__ src, const int* __restrict__ dst,
                           const float* __restrict__ c) {
    int e = blockIdx.x * blockDim.x + threadIdx.x;
    if (e >= N_EDGES) return;
    int s = src[e], t = dst[e];
    atomicAdd(&g_cnt[t], 1);
    float4 s0 = __ldg((const float4*)&c[s * EMB]);
    float4 s1 = __ldg((const float4*)&c[s * EMB + 4]);
    float4 t0 = __ldg((const float4*)&c[t * EMB]);
    float4 t1 = __ldg((const float4*)&c[t * EMB + 4]);
    float4 d0 = make_float4(s0.x - t0.x, s0.y - t0.y, s0.z - t0.z, s0.w - t0.w);
    float4 d1 = make_float4(s1.x - t1.x, s1.y - t1.y, s1.z - t1.z, s1.w - t1.w);
    float nn = d0.x * d0.x + d0.y * d0.y + d0.z * d0.z + d0.w * d0.w
             + d1.x * d1.x + d1.y * d1.y + d1.z * d1.z + d1.w * d1.w;
    float sc = 1.0f / fmaxf(sqrtf(nn), 1e-12f);
    d0.x *= sc; d0.y *= sc; d0.z *= sc; d0.w *= sc;
    d1.x *= sc; d1.y *= sc; d1.z *= sc; d1.w *= sc;
    *(float4*)&g_D[(size_t)e * EMB]     = d0;
    *(float4*)&g_D[(size_t)e * EMB + 4] = d1;
}

// single-block scan over counts -> rowptr; also gids histogram -> g_gcntf
__global__ void k_scan(const int* __restrict__ gids) {
    const int PER = 25;
    __shared__ int wsum[32];
    __shared__ int hcnt[N_GRAPHS];
    int tid = threadIdx.x, lane = tid & 31, wid = tid >> 5;
    if (tid < N_GRAPHS) hcnt[tid] = 0;
    __syncthreads();
    int base = tid * PER;
    int v[PER];
    int s = 0;
    #pragma unroll
    for (int j = 0; j < PER; j++) {
        int i = base + j;
        int cv = 0;
        if (i < N_NODES) {
            cv = g_cnt[i];
            atomicAdd(&hcnt[__ldg(&gids[i])], 1);
        }
        v[j] = s;
        s += cv;
    }
    int x = s;
    #pragma unroll
    for (int o = 1; o < 32; o <<= 1) {
        int t = __shfl_up_sync(0xffffffffu, x, o);
        if (lane >= o) x += t;
    }
    if (lane == 31) wsum[wid] = x;
    __syncthreads();
    if (wid == 0) {
        int w = wsum[lane];
        #pragma unroll
        for (int o = 1; o < 32; o <<= 1) {
            int t = __shfl_up_sync(0xffffffffu, w, o);
            if (lane >= o) w += t;
        }
        wsum[lane] = w;
    }
    __syncthreads();
    int off = x - s + (wid > 0 ? wsum[wid - 1] : 0);
    #pragma unroll
    for (int j = 0; j < PER; j++) {
        int i = base + j;
        if (i <= N_NODES) g_rowptr[i] = off + v[j];
    }
    if (tid < N_GRAPHS) g_gcntf[tid] = (float)hcnt[tid];
}

// scatter edge -> CSR slot; only 8 bytes scattered per edge
__global__ void k_scatter(const int* __restrict__ src, const int* __restrict__ dst) {
    int e = blockIdx.x * blockDim.x + threadIdx.x;
    if (e >= N_EDGES) return;
    int s = src[e], t = dst[e];
    int p = g_rowptr[t] + atomicAdd(&g_cur[t], 1);
    g_se[p] = make_int2(s, e);
}

// ======== FUSED layer kernel: gather(+BN affine of prev layers) + GEMM ======
// MODE 0: h = feature;  MODE 1: h = s0*R0+b0;  MODE 2: h = s1*R1+b1 + s0*R0+b0
// Epilogue: relu -> R_L, column stats, per-graph pooled sums of relu(agg).
template <int MODE>
__global__ void __launch_bounds__(LAYER_THREADS)
k_layer(const float* __restrict__ feat, const float* __restrict__ W,
        const int* __restrict__ gids,
        const float* __restrict__ gm0, const float* __restrict__ bt0,
        const float* __restrict__ gm1, const float* __restrict__ bt1) {
    extern __shared__ unsigned smem_u[];
    unsigned* As = smem_u;                    // TM * ASTRIDE
    unsigned* Ws = smem_u + TM * ASTRIDE;     // 32 * WSTRIDE
    int tid = threadIdx.x;
    int lane = tid & 31, w = tid >> 5;
    int rowBase = blockIdx.x * TM;

    // BN affine coefficients of previous layers for this lane's two columns
    float s0a = 0.f, b0a = 0.f, s0b = 0.f, b0b = 0.f;
    float s1a = 0.f, b1a = 0.f, s1b = 0.f, b1b = 0.f;
    if (MODE >= 1) {
        int ka = lane, kb = lane + 32;
        float mua = g_sumsL[ka] * INV_N, mub = g_sumsL[kb] * INV_N;
        float va = g_sumsqL[ka] * INV_N - mua * mua;
        float vb = g_sumsqL[kb] * INV_N - mub * mub;
        float ra = rsqrtf(va + BN_EPS), rb = rsqrtf(vb + BN_EPS);
        s0a = __ldg(&gm0[ka]) * ra;  b0a = __ldg(&bt0[ka]) - mua * s0a;
        s0b = __ldg(&gm0[kb]) * rb;  b0b = __ldg(&bt0[kb]) - mub * s0b;
    }
    if (MODE == 2) {
        int ka = lane, kb = lane + 32;
        float mua = g_sumsL[HID + ka] * INV_N, mub = g_sumsL[HID + kb] * INV_N;
        float va = g_sumsqL[HID + ka] * INV_N - mua * mua;
        float vb = g_sumsqL[HID + kb] * INV_N - mub * mub;
        float ra = rsqrtf(va + BN_EPS), rb = rsqrtf(vb + BN_EPS);
        s1a = __ldg(&gm1[ka]) * ra;  b1a = __ldg(&bt1[ka]) - mua * s1a;
        s1b = __ldg(&gm1[kb]) * rb;  b1b = __ldg(&bt1[kb]) - mub * s1b;
    }

    // ---- phase 1: aggregation (warp w -> tile rows 2w, 2w+1) ----
    #pragma unroll
    for (int q = 0; q < 2; q++) {
        int r = w * 2 + q;
        int node = rowBase + r;
        float a0[EMB], a1[EMB];
        #pragma unroll
        for (int i = 0; i < EMB; i++) { a0[i] = 0.f; a1[i] = 0.f; }
        if (node < N_NODES) {
            int e0 = g_rowptr[node], e1 = g_rowptr[node + 1];
            #pragma unroll 2
            for (int e = e0; e < e1; e++) {
                int2 se = __ldg(&g_se[e]);
                float4 d0 = __ldg((const float4*)&g_D[(size_t)se.y * EMB]);
                float4 d1 = __ldg((const float4*)&g_D[(size_t)se.y * EMB + 4]);
                float h0, h1;
                if (MODE == 0) {
                    h0 = __ldg(&feat[se.x * HID + lane]);
                    h1 = __ldg(&feat[se.x * HID + 32 + lane]);
                } else if (MODE == 1) {
                    h0 = fmaf(s0a, __ldg(&g_R0[se.x * HID + lane]), b0a);
                    h1 = fmaf(s0b, __ldg(&g_R0[se.x * HID + 32 + lane]), b0b);
                } else {
                    h0 = fmaf(s0a, __ldg(&g_R0[se.x * HID + lane]), b0a)
                       + fmaf(s1a, __ldg(&g_R1[se.x * HID + lane]), b1a);
                    h1 = fmaf(s0b, __ldg(&g_R0[se.x * HID + 32 + lane]), b0b)
                       + fmaf(s1b, __ldg(&g_R1[se.x * HID + 32 + lane]), b1b);
                }
                a0[0] += d0.x * h0;  a1[0] += d0.x * h1;
                a0[1] += d0.y * h0;  a1[1] += d0.y * h1;
                a0[2] += d0.z * h0;  a1[2] += d0.z * h1;
                a0[3] += d0.w * h0;  a1[3] += d0.w * h1;
                a0[4] += d1.x * h0;  a1[4] += d1.x * h1;
                a0[5] += d1.y * h0;  a1[5] += d1.y * h1;
                a0[6] += d1.z * h0;  a1[6] += d1.z * h1;
                a0[7] += d1.w * h0;  a1[7] += d1.w * h1;
            }
        }
        #pragma unroll
        for (int i = 0; i < EMB; i++) {
            As[r * ASTRIDE + i * HID + lane]      = tf32cvt(a0[i]);
            As[r * ASTRIDE + i * HID + 32 + lane] = tf32cvt(a1[i]);
        }
    }
    __syncthreads();

    // ---- phase 2: GEMM (32 x 64 x 512) ----
    int g = lane >> 2, tig = lane & 3;
    int rg = w >> 3, wn = w & 7;
    int arow0 = (rg * 16 + g) * ASTRIDE;
    int arow1 = (rg * 16 + g + 8) * ASTRIDE;
    float acc[4] = {0.f, 0.f, 0.f, 0.f};
    for (int kb = 0; kb < KDIM; kb += 32) {
        {
            int k = tid >> 4, q = tid & 15;
            float4 v = *(const float4*)&W[(kb + k) * HID + q * 4];
            Ws[k * WSTRIDE + q * 4]     = tf32cvt(v.x);
            Ws[k * WSTRIDE + q * 4 + 1] = tf32cvt(v.y);
            Ws[k * WSTRIDE + q * 4 + 2] = tf32cvt(v.z);
            Ws[k * WSTRIDE + q * 4 + 3] = tf32cvt(v.w);
        }
        __syncthreads();
        #pragma unroll
        for (int kk = 0; kk < 4; kk++) {
            int kc = kb + kk * 8;
            unsigned a0 = As[arow0 + kc + tig];
            unsigned a1 = As[arow1 + kc + tig];
            unsigned a2 = As[arow0 + kc + tig + 4];
            unsigned a3 = As[arow1 + kc + tig + 4];
            unsigned b0 = Ws[(kk * 8 + tig) * WSTRIDE + wn * 8 + g];
            unsigned b1 = Ws[(kk * 8 + tig + 4) * WSTRIDE + wn * 8 + g];
            mma_tf32(acc, a0, a1, a2, a3, b0, b1);
        }
        __syncthreads();
    }

    // ---- epilogue: relu + store + column stats + per-graph pooled sums ----
    float* Rout = (MODE == 0) ? g_R0 : ((MODE == 1) ? g_R1 : g_R2);
    int r0 = rowBase + rg * 16 + g, r1 = r0 + 8;
    int col = wn * 8 + tig * 2;
    float v0 = fmaxf(acc[0], 0.f), v1 = fmaxf(acc[1], 0.f);
    float v2 = fmaxf(acc[2], 0.f), v3 = fmaxf(acc[3], 0.f);
    if (r0 < N_NODES) *(float2*)&Rout[r0 * HID + col] = make_float2(v0, v1);
    if (r1 < N_NODES) *(float2*)&Rout[r1 * HID + col] = make_float2(v2, v3);

    // column stats (sum, sumsq) via warp butterfly over rows
    float cS0 = v0 + v2, cS1 = v1 + v3;
    float cQ0 = v0 * v0 + v2 * v2, cQ1 = v1 * v1 + v3 * v3;
    #pragma unroll
    for (int o = 16; o >= 4; o >>= 1) {
        cS0 += __shfl_xor_sync(0xffffffffu, cS0, o);
        cS1 += __shfl_xor_sync(0xffffffffu, cS1, o);
        cQ0 += __shfl_xor_sync(0xffffffffu, cQ0, o);
        cQ1 += __shfl_xor_sync(0xffffffffu, cQ1, o);
    }
    if (g == 0) {
        atomicAdd(&g_sumsL[MODE * HID + col], cS0);
        atomicAdd(&g_sumsL[MODE * HID + col + 1], cS1);
        atomicAdd(&g_sumsqL[MODE * HID + col], cQ0);
        atomicAdd(&g_sumsqL[MODE * HID + col + 1], cQ1);
    }

    // per-graph pooled sums of relu(agg) via smem (reuse As region)
    float* ps = (float*)smem_u;   // N_GRAPHS*HID = 1024 floats
    for (int i = tid; i < N_GRAPHS * HID; i += LAYER_THREADS) ps[i] = 0.f;
    __syncthreads();
    if (r0 < N_NODES) {
        int gg = __ldg(&gids[r0]);
        atomicAdd(&ps[gg * HID + col], v0);
        atomicAdd(&ps[gg * HID + col + 1], v1);
    }
    if (r1 < N_NODES) {
        int gg = __ldg(&gids[r1]);
        atomicAdd(&ps[gg * HID + col], v2);
        atomicAdd(&ps[gg * HID + col + 1], v3);
    }
    __syncthreads();
    int lastRow = rowBase + TM - 1;
    if (lastRow >= N_NODES) lastRow = N_NODES - 1;
    int gmin = __ldg(&gids[rowBase]);
    int gmax = __ldg(&gids[lastRow]);
    int span = (gmax - gmin + 1) * HID;
    for (int i = tid; i < span; i += LAYER_THREADS)
        atomicAdd(&g_poolR[MODE * N_GRAPHS * HID + gmin * HID + i], ps[gmin * HID + i]);
}

// ---------------- final: pooled recursion + classifier x3 ------------------
__global__ void k_finish(const float* __restrict__ gm0, const float* __restrict__ bt0,
                         const float* __restrict__ gm1, const float* __restrict__ bt1,
                         const float* __restrict__ gm2, const float* __restrict__ bt2,
                         const float* __restrict__ cW1, const float* __restrict__ cb1,
                         const float* __restrict__ cg1, const float* __restrict__ cbt1,
                         const float* __restrict__ cW2, const float* __restrict__ cb2,
                         float* __restrict__ out) {
    __shared__ float pooled[N_GRAPHS * HID];
    __shared__ float y[N_GRAPHS * 32];
    __shared__ float mus[32], rss[32];
    __shared__ float logits[N_GRAPHS * N_CLASSES];
    int tid = threadIdx.x;    // 512
    if (tid < N_GRAPHS * N_CLASSES) logits[tid] = 0.f;

    const float* gms[3] = { gm0, gm1, gm2 };
    const float* bts[3] = { bt0, bt1, bt2 };

    for (int L = 0; L < 3; L++) {
        // pooled_L = s_L * poolR_L + cnt_g * b_L + (L>0 ? pooled_{L-1} : 0)
        __syncthreads();
        for (int i = tid; i < N_GRAPHS * HID; i += 512) {
            int g = i >> 6, k = i & 63;
            float mu = g_sumsL[L * HID + k] * INV_N;
            float var = g_sumsqL[L * HID + k] * INV_N - mu * mu;
            float rstd = rsqrtf(var + BN_EPS);
            float s = __ldg(&gms[L][k]) * rstd;
            float b = __ldg(&bts[L][k]) - mu * s;
            float p = s * g_poolR[L * N_GRAPHS * HID + i] + g_gcntf[g] * b;
            if (L > 0) p += pooled[i];
            pooled[i] = p;
        }
        __syncthreads();
        {
            int r = tid >> 5, c = tid & 31;
            float acc = cb1[c];
            #pragma unroll 8
            for (int j = 0; j < HID; j++) acc += pooled[r * HID + j] * cW1[j * 32 + c];
            y[r * 32 + c] = acc;
        }
        __syncthreads();
        if (tid < 32) {
            float s = 0.f, s2 = 0.f;
            #pragma unroll
            for (int r = 0; r < N_GRAPHS; r++) {
                float vv = y[r * 32 + tid];
                s += vv; s2 += vv * vv;
            }
            float m = s / (float)N_GRAPHS;
            float vr = s2 / (float)N_GRAPHS - m * m;
            mus[tid] = m;
            rss[tid] = rsqrtf(vr + BN_EPS);
        }
        __syncthreads();
        {
            int r = tid >> 5, c = tid & 31;
            float vv = cg1[c] * (y[r * 32 + c] - mus[c]) * rss[c] + cbt1[c];
            y[r * 32 + c] = fmaxf(vv, 0.f);
        }
        __syncthreads();
        if (tid < N_GRAPHS * N_CLASSES) {
            int r = tid / N_CLASSES, c = tid % N_CLASSES;
            float acc = cb2[c];
            #pragma unroll
            for (int j = 0; j < 32; j++) acc += y[r * 32 + j] * cW2[j * N_CLASSES + c];
            logits[tid] += acc;
        }
    }
    __syncthreads();
    if (tid < N_GRAPHS * N_CLASSES) out[tid] = logits[tid];
}

// ---------------- launcher -------------------------------------------------
extern "C" void kernel_launch(void* const* d_in, const int* in_sizes, int n_in,
                              void* d_out, int out_size) {
    const float* feature = (const float*)d_in[0];
    const float* spemb   = (const float*)d_in[1];
    const int*   src     = (const int*)d_in[2];
    const int*   dst     = (const int*)d_in[3];
    const int*   gids    = (const int*)d_in[4];
    const float* W[3]  = { (const float*)d_in[5], (const float*)d_in[6], (const float*)d_in[7] };
    const float* gm[3] = { (const float*)d_in[8], (const float*)d_in[10], (const float*)d_in[12] };
    const float* bt[3] = { (const float*)d_in[9], (const float*)d_in[11], (const float*)d_in[13] };
    const float* cW1  = (const float*)d_in[14];
    const float* cb1  = (const float*)d_in[15];
    const float* cg1  = (const float*)d_in[16];
    const float* cbt1 = (const float*)d_in[17];
    const float* cW2  = (const float*)d_in[18];
    const float* cb2  = (const float*)d_in[19];
    float* out = (float*)d_out;

    static int smem_set = 0;
    if (!smem_set) {
        cudaFuncSetAttribute(k_layer<0>, cudaFuncAttributeMaxDynamicSharedMemorySize, LAYER_SMEM);
        cudaFuncSetAttribute(k_layer<1>, cudaFuncAttributeMaxDynamicSharedMemorySize, LAYER_SMEM);
        cudaFuncSetAttribute(k_layer<2>, cudaFuncAttributeMaxDynamicSharedMemorySize, LAYER_SMEM);
        smem_set = 1;
    }

    int nblk = (N_NODES + TM - 1) / TM;
    k_zero_cc<<<(N_NODES + 255) / 256, 256>>>();
    k_hist_dir<<<(N_EDGES + 255) / 256, 256>>>(src, dst, spemb);
    k_scan<<<1, 1024>>>(gids);
    k_scatter<<<(N_EDGES + 255) / 256, 256>>>(src, dst);

    k_layer<0><<<nblk, LAYER_THREADS, LAYER_SMEM>>>(feature, W[0], gids,
                                                    gm[0], bt[0], gm[1], bt[1]);
    k_layer<1><<<nblk, LAYER_THREADS, LAYER_SMEM>>>(feature, W[1], gids,
                                                    gm[0], bt[0], gm[1], bt[1]);
    k_layer<2><<<nblk, LAYER_THREADS, LAYER_SMEM>>>(feature, W[2], gids,
                                                    gm[0], bt[0], gm[1], bt[1]);
    k_finish<<<1, 512>>>(gm[0], bt[0], gm[1], bt[1], gm[2], bt[2],
                         cW1, cb1, cg1, cbt1, cW2, cb2, out);
}

// round 9
// speedup vs baseline: 1.0221x; 1.0221x over previous
#include <cuda_runtime.h>
#include <cuda_bf16.h>
#include <math.h>

#define N_NODES 25000
#define N_EDGES 400000
#define HID 64
#define EMB 8
#define N_GRAPHS 16
#define N_CLASSES 10
#define KDIM 512     /* EMB*HID */
#define TM 32        /* node tile per block in fused layer kernel */
#define ASTRIDE 516  /* smem A row stride (mod 32 == 4 -> conflict-free frags) */
#define WSTRIDE 72   /* smem W row stride (mod 32 == 8 -> conflict-free frags) */
#define LAYER_THREADS 512
#define LAYER_SMEM ((TM * ASTRIDE + 32 * WSTRIDE) * 4)

// ---------------- scratch (device globals; no allocation allowed) ----------
__device__ float g_hA[N_NODES * HID];
__device__ float g_hB[N_NODES * HID];
__device__ float g_R[N_NODES * HID];              // relu(agg)
__device__ float g_D[(size_t)N_EDGES * EMB];      // directions, ORIGINAL edge order
__device__ float g_Dc[(size_t)N_EDGES * EMB];     // directions, CSR order
__device__ int   g_srcs[N_EDGES];                 // CSR-ordered src
__device__ int2  g_se[N_EDGES];                   // CSR-ordered {src, edge_id}
__device__ int   g_rowptr[N_NODES + 1];
__device__ int   g_cnt[N_NODES];
__device__ int   g_cur[N_NODES];
__device__ float g_sums[HID];
__device__ float g_sumsq[HID];
__device__ float g_pooled[N_GRAPHS * HID];
__device__ int   g_done;

// ---------------- tf32 helpers ---------------------------------------------
__device__ __forceinline__ unsigned tf32cvt(float x) {
    unsigned r;
    asm("cvt.rna.tf32.f32 %0, %1;" : "=r"(r) : "f"(x));
    return r;
}
__device__ __forceinline__ void mma_tf32(float* c,
                                         unsigned a0, unsigned a1, unsigned a2, unsigned a3,
                                         unsigned b0, unsigned b1) {
    asm volatile(
        "mma.sync.aligned.m16n8k8.row.col.f32.tf32.tf32.f32 "
        "{%0,%1,%2,%3}, {%4,%5,%6,%7}, {%8,%9}, {%0,%1,%2,%3};"
        : "+f"(c[0]), "+f"(c[1]), "+f"(c[2]), "+f"(c[3])
        : "r"(a0), "r"(a1), "r"(a2), "r"(a3), "r"(b0), "r"(b1));
}

// ---------------- CSR build ------------------------------------------------
__global__ void k_zero_cc() {
    int i = blockIdx.x * blockDim.x + threadIdx.x;
    if (i < N_NODES) { g_cnt[i] = 0; g_cur[i] = 0; }
    if (blockIdx.x == 0) {
        int t = threadIdx.x;
        if (t < HID) { g_sums[t] = 0.f; g_sumsq[t] = 0.f; }
        if (t == 0) g_done = 0;
        for (int j = t; j < N_GRAPHS * HID; j += blockDim.x) g_pooled[j] = 0.f;
    }
}

// histogram of dst + per-edge normalized direction (coalesced write, edge order)
__global__ void k_hist_dir(const int* __restrict__ src, const int* __restrict__ dst,
                           const float* __restrict__ c) {
    int e = blockIdx.x * blockDim.x + threadIdx.x;
    if (e >= N_EDGES) return;
    int s = src[e], t = dst[e];
    atomicAdd(&g_cnt[t], 1);
    float4 s0 = __ldg((const float4*)&c[s * EMB]);
    float4 s1 = __ldg((const float4*)&c[s * EMB + 4]);
    float4 t0 = __ldg((const float4*)&c[t * EMB]);
    float4 t1 = __ldg((const float4*)&c[t * EMB + 4]);
    float4 d0 = make_float4(s0.x - t0.x, s0.y - t0.y, s0.z - t0.z, s0.w - t0.w);
    float4 d1 = make_float4(s1.x - t1.x, s1.y - t1.y, s1.z - t1.z, s1.w - t1.w);
    float nn = d0.x * d0.x + d0.y * d0.y + d0.z * d0.z + d0.w * d0.w
             + d1.x * d1.x + d1.y * d1.y + d1.z * d1.z + d1.w * d1.w;
    float sc = 1.0f / fmaxf(sqrtf(nn), 1e-12f);
    d0.x *= sc; d0.y *= sc; d0.z *= sc; d0.w *= sc;
    d1.x *= sc; d1.y *= sc; d1.z *= sc; d1.w *= sc;
    *(float4*)&g_D[(size_t)e * EMB]     = d0;
    *(float4*)&g_D[(size_t)e * EMB + 4] = d1;
}

// single-block scan: 1024 threads x 25 contiguous counts each
__global__ void k_scan() {
    const int PER = 25;
    __shared__ int wsum[32];
    int tid = threadIdx.x, lane = tid & 31, wid = tid >> 5;
    int base = tid * PER;
    int v[PER];
    int s = 0;
    #pragma unroll
    for (int j = 0; j < PER; j++) {
        int i = base + j;
        int cv = (i < N_NODES) ? g_cnt[i] : 0;
        v[j] = s;
        s += cv;
    }
    int x = s;
    #pragma unroll
    for (int o = 1; o < 32; o <<= 1) {
        int t = __shfl_up_sync(0xffffffffu, x, o);
        if (lane >= o) x += t;
    }
    if (lane == 31) wsum[wid] = x;
    __syncthreads();
    if (wid == 0) {
        int w = wsum[lane];
        #pragma unroll
        for (int o = 1; o < 32; o <<= 1) {
            int t = __shfl_up_sync(0xffffffffu, w, o);
            if (lane >= o) w += t;
        }
        wsum[lane] = w;
    }
    __syncthreads();
    int off = x - s + (wid > 0 ? wsum[wid - 1] : 0);
    #pragma unroll
    for (int j = 0; j < PER; j++) {
        int i = base + j;
        if (i <= N_NODES) g_rowptr[i] = off + v[j];
    }
}

// scatter edge -> CSR slot; only 8 bytes scattered per edge
__global__ void k_scatter(const int* __restrict__ src, const int* __restrict__ dst) {
    int e = blockIdx.x * blockDim.x + threadIdx.x;
    if (e >= N_EDGES) return;
    int s = src[e], t = dst[e];
    int p = g_rowptr[t] + atomicAdd(&g_cur[t], 1);
    g_se[p] = make_int2(s, e);
}

// reorder payloads into CSR order: coalesced stores, random reads (paid once)
__global__ void k_reorder() {
    int p = blockIdx.x * blockDim.x + threadIdx.x;
    if (p >= N_EDGES) return;
    int2 se = g_se[p];
    g_srcs[p] = se.x;
    float4 d0 = __ldg((const float4*)&g_D[(size_t)se.y * EMB]);
    float4 d1 = __ldg((const float4*)&g_D[(size_t)se.y * EMB + 4]);
    *(float4*)&g_Dc[(size_t)p * EMB]     = d0;
    *(float4*)&g_Dc[(size_t)p * EMB + 4] = d1;
}

// ======== FUSED layer kernel: edge-agg (-> smem) + tf32 GEMM + BN stats =====
// Block: 512 threads (16 warps), 32-node tile.
// Phase 1: warp w aggregates nodes rowBase+2w, rowBase+2w+1 -> tf32 smem A rows.
//          (D and srcs are read in CSR order: sequential, L1-friendly.)
// Phase 2: W tiles streamed with REGISTER PREFETCH (LDG overlaps MMA);
//          warp w = (rg = w>>3, wn = w&7) computes rows rg*16.. x cols wn*8..
__global__ void __launch_bounds__(LAYER_THREADS)
k_layer(const float* __restrict__ feat, int hsel, const float* __restrict__ W) {
    extern __shared__ unsigned smem_u[];
    unsigned* As = smem_u;                    // TM * ASTRIDE
    unsigned* Ws = smem_u + TM * ASTRIDE;     // 32 * WSTRIDE
    const float* __restrict__ h = (hsel == 0) ? feat : ((hsel == 1) ? g_hA : g_hB);
    int tid = threadIdx.x;
    int lane = tid & 31, w = tid >> 5;
    int rowBase = blockIdx.x * TM;

    // prefetch W tile 0 into registers before gather (latency fully hidden)
    int wk = tid >> 4, wq = tid & 15;
    float4 wreg = __ldg((const float4*)&W[wk * HID + wq * 4]);

    // ---- phase 1: aggregation (warp w -> tile rows 2w, 2w+1) ----
    #pragma unroll
    for (int q = 0; q < 2; q++) {
        int r = w * 2 + q;
        int node = rowBase + r;
        float a0[EMB], a1[EMB];
        #pragma unroll
        for (int i = 0; i < EMB; i++) { a0[i] = 0.f; a1[i] = 0.f; }
        if (node < N_NODES) {
            int e0 = g_rowptr[node], e1 = g_rowptr[node + 1];
            #pragma unroll 2
            for (int e = e0; e < e1; e++) {
                int sx = __ldg(&g_srcs[e]);
                float4 d0 = __ldg((const float4*)&g_Dc[(size_t)e * EMB]);
                float4 d1 = __ldg((const float4*)&g_Dc[(size_t)e * EMB + 4]);
                float h0 = __ldg(&h[sx * HID + lane]);
                float h1 = __ldg(&h[sx * HID + 32 + lane]);
                a0[0] += d0.x * h0;  a1[0] += d0.x * h1;
                a0[1] += d0.y * h0;  a1[1] += d0.y * h1;
                a0[2] += d0.z * h0;  a1[2] += d0.z * h1;
                a0[3] += d0.w * h0;  a1[3] += d0.w * h1;
                a0[4] += d1.x * h0;  a1[4] += d1.x * h1;
                a0[5] += d1.y * h0;  a1[5] += d1.y * h1;
                a0[6] += d1.z * h0;  a1[6] += d1.z * h1;
                a0[7] += d1.w * h0;  a1[7] += d1.w * h1;
            }
        }
        #pragma unroll
        for (int i = 0; i < EMB; i++) {
            As[r * ASTRIDE + i * HID + lane]      = tf32cvt(a0[i]);
            As[r * ASTRIDE + i * HID + 32 + lane] = tf32cvt(a1[i]);
        }
    }
    __syncthreads();

    // ---- phase 2: GEMM (32 x 64 x 512), reg-prefetched W tiles ----
    int g = lane >> 2, tig = lane & 3;
    int rg = w >> 3, wn = w & 7;
    int arow0 = (rg * 16 + g) * ASTRIDE;
    int arow1 = (rg * 16 + g + 8) * ASTRIDE;
    float acc[4] = {0.f, 0.f, 0.f, 0.f};
    for (int kb = 0; kb < KDIM; kb += 32) {
        Ws[wk * WSTRIDE + wq * 4]     = tf32cvt(wreg.x);
        Ws[wk * WSTRIDE + wq * 4 + 1] = tf32cvt(wreg.y);
        Ws[wk * WSTRIDE + wq * 4 + 2] = tf32cvt(wreg.z);
        Ws[wk * WSTRIDE + wq * 4 + 3] = tf32cvt(wreg.w);
        __syncthreads();
        if (kb + 32 < KDIM)
            wreg = __ldg((const float4*)&W[(kb + 32 + wk) * HID + wq * 4]);
        #pragma unroll
        for (int kk = 0; kk < 4; kk++) {
            int kc = kb + kk * 8;
            unsigned a0 = As[arow0 + kc + tig];
            unsigned a1 = As[arow1 + kc + tig];
            unsigned a2 = As[arow0 + kc + tig + 4];
            unsigned a3 = As[arow1 + kc + tig + 4];
            unsigned b0 = Ws[(kk * 8 + tig) * WSTRIDE + wn * 8 + g];
            unsigned b1 = Ws[(kk * 8 + tig + 4) * WSTRIDE + wn * 8 + g];
            mma_tf32(acc, a0, a1, a2, a3, b0, b1);
        }
        __syncthreads();
    }

    // ---- epilogue: relu + store + column stats ----
    int r0 = rowBase + rg * 16 + g, r1 = r0 + 8;
    int col = wn * 8 + tig * 2;
    float v0 = fmaxf(acc[0], 0.f), v1 = fmaxf(acc[1], 0.f);
    float v2 = fmaxf(acc[2], 0.f), v3 = fmaxf(acc[3], 0.f);
    if (r0 < N_NODES) *(float2*)&g_R[r0 * HID + col] = make_float2(v0, v1);
    if (r1 < N_NODES) *(float2*)&g_R[r1 * HID + col] = make_float2(v2, v3);
    float cS0 = v0 + v2, cS1 = v1 + v3;
    float cQ0 = v0 * v0 + v2 * v2, cQ1 = v1 * v1 + v3 * v3;
    #pragma unroll
    for (int o = 16; o >= 4; o >>= 1) {
        cS0 += __shfl_xor_sync(0xffffffffu, cS0, o);
        cS1 += __shfl_xor_sync(0xffffffffu, cS1, o);
        cQ0 += __shfl_xor_sync(0xffffffffu, cQ0, o);
        cQ1 += __shfl_xor_sync(0xffffffffu, cQ1, o);
    }
    if (g == 0) {
        atomicAdd(&g_sums[col], cS0);
        atomicAdd(&g_sums[col + 1], cS1);
        atomicAdd(&g_sumsq[col], cQ0);
        atomicAdd(&g_sumsq[col + 1], cQ1);
    }
}

// ------- BN normalize + shortcut + pooling + (last block) classifier -------
// Last block also re-zeros g_sums/g_sumsq/g_pooled/g_done for the next layer.
__global__ void k_norm_pool(const float* __restrict__ feat, int hinsel, int houtsel,
                            const float* __restrict__ gamma, const float* __restrict__ beta,
                            const int* __restrict__ gids, int shortcut,
                            const float* __restrict__ cW1, const float* __restrict__ cb1,
                            const float* __restrict__ cg1, const float* __restrict__ cbt1,
                            const float* __restrict__ cW2, const float* __restrict__ cb2,
                            float* __restrict__ out, int accumulate) {
    const float* __restrict__ hin = (hinsel == 0) ? feat : ((hinsel == 1) ? g_hA : g_hB);
    float* hout = (houtsel == 1) ? g_hA : g_hB;
    int tid = threadIdx.x;        // 512 -> 8 nodes x 64 cols per block
    int k = tid & 63, nl = tid >> 6;
    int n = blockIdx.x * 8 + nl;  // 3125*8 == 25000 exactly

    __shared__ float ps[N_GRAPHS * HID];
    for (int i = tid; i < N_GRAPHS * HID; i += 512) ps[i] = 0.f;
    __syncthreads();

    const float inv = 1.0f / (float)N_NODES;
    float mu = g_sums[k] * inv;
    float var = g_sumsq[k] * inv - mu * mu;
    float rstd = rsqrtf(var + 1e-5f);
    float v = gamma[k] * (g_R[n * HID + k] - mu) * rstd + beta[k];
    if (shortcut) v += hin[n * HID + k];
    hout[n * HID + k] = v;

    int g = gids[n];
    atomicAdd(&ps[g * HID + k], v);
    __syncthreads();

    int gmin = gids[blockIdx.x * 8];
    int gmax = gids[blockIdx.x * 8 + 7];
    int span = (gmax - gmin + 1) * HID;
    for (int i = tid; i < span; i += 512)
        atomicAdd(&g_pooled[gmin * HID + i], ps[gmin * HID + i]);

    // ---- last-block classifier + state reset ----
    __shared__ int s_last;
    __threadfence();
    __syncthreads();
    if (tid == 0) s_last = (atomicAdd(&g_done, 1) == (int)gridDim.x - 1) ? 1 : 0;
    __syncthreads();
    if (!s_last) return;

    __shared__ float xp[N_GRAPHS * HID];
    __shared__ float y[N_GRAPHS * 32];
    __shared__ float mus[32], rss[32];
    for (int i = tid; i < N_GRAPHS * HID; i += 512) {
        xp[i] = g_pooled[i];
        g_pooled[i] = 0.f;                 // reset for next layer
    }
    if (tid < HID) { g_sums[tid] = 0.f; g_sumsq[tid] = 0.f; }
    if (tid == 0) g_done = 0;
    __syncthreads();
    {
        int r = tid >> 5, c = tid & 31;
        float acc = cb1[c];
        #pragma unroll 8
        for (int j = 0; j < HID; j++) acc += xp[r * HID + j] * cW1[j * 32 + c];
        y[r * 32 + c] = acc;
    }
    __syncthreads();
    if (tid < 32) {
        float s = 0.f, s2 = 0.f;
        #pragma unroll
        for (int r = 0; r < N_GRAPHS; r++) {
            float vv = y[r * 32 + tid];
            s += vv; s2 += vv * vv;
        }
        float m = s / (float)N_GRAPHS;
        float vr = s2 / (float)N_GRAPHS - m * m;
        mus[tid] = m;
        rss[tid] = rsqrtf(vr + 1e-5f);
    }
    __syncthreads();
    {
        int r = tid >> 5, c = tid & 31;
        float vv = cg1[c] * (y[r * 32 + c] - mus[c]) * rss[c] + cbt1[c];
        y[r * 32 + c] = fmaxf(vv, 0.f);
    }
    __syncthreads();
    if (tid < N_GRAPHS * N_CLASSES) {
        int r = tid / N_CLASSES, c = tid % N_CLASSES;
        float acc = cb2[c];
        #pragma unroll
        for (int j = 0; j < 32; j++) acc += y[r * 32 + j] * cW2[j * N_CLASSES + c];
        if (accumulate) out[r * N_CLASSES + c] += acc;
        else            out[r * N_CLASSES + c] = acc;
    }
}

// ---------------- launcher -------------------------------------------------
extern "C" void kernel_launch(void* const* d_in, const int* in_sizes, int n_in,
                              void* d_out, int out_size) {
    const float* feature = (const float*)d_in[0];
    const float* spemb   = (const float*)d_in[1];
    const int*   src     = (const int*)d_in[2];
    const int*   dst     = (const int*)d_in[3];
    const int*   gids    = (const int*)d_in[4];
    const float* W[3]  = { (const float*)d_in[5], (const float*)d_in[6], (const float*)d_in[7] };
    const float* gm[3] = { (const float*)d_in[8], (const float*)d_in[10], (const float*)d_in[12] };
    const float* bt[3] = { (const float*)d_in[9], (const float*)d_in[11], (const float*)d_in[13] };
    const float* cW1  = (const float*)d_in[14];
    const float* cb1  = (const float*)d_in[15];
    const float* cg1  = (const float*)d_in[16];
    const float* cbt1 = (const float*)d_in[17];
    const float* cW2  = (const float*)d_in[18];
    const float* cb2  = (const float*)d_in[19];
    float* out = (float*)d_out;

    static int smem_set = 0;
    if (!smem_set) {
        cudaFuncSetAttribute(k_layer, cudaFuncAttributeMaxDynamicSharedMemorySize,
                             LAYER_SMEM);
        smem_set = 1;
    }

    k_zero_cc<<<(N_NODES + 255) / 256, 256>>>();
    k_hist_dir<<<(N_EDGES + 255) / 256, 256>>>(src, dst, spemb);
    k_scan<<<1, 1024>>>();
    k_scatter<<<(N_EDGES + 255) / 256, 256>>>(src, dst);
    k_reorder<<<(N_EDGES + 255) / 256, 256>>>();

    int hin = 0, hout = 1;
    for (int L = 0; L < 3; L++) {
        k_layer<<<(N_NODES + TM - 1) / TM, LAYER_THREADS, LAYER_SMEM>>>(feature, hin, W[L]);
        k_norm_pool<<<N_NODES / 8, 512>>>(feature, hin, hout, gm[L], bt[L], gids,
                                          L > 0 ? 1 : 0,
                                          cW1, cb1, cg1, cbt1, cW2, cb2,
                                          out, L > 0 ? 1 : 0);
        hin = hout;
        hout = (hout == 1) ? 2 : 1;
    }
}

// round 10
// speedup vs baseline: 1.0570x; 1.0342x over previous
#include <cuda_runtime.h>
#include <cuda_bf16.h>
#include <math.h>

#define N_NODES 25000
#define N_EDGES 400000
#define HID 64
#define EMB 8
#define N_GRAPHS 16
#define N_CLASSES 10
#define KDIM 512     /* EMB*HID */
#define TM 32        /* node tile per block in fused layer kernel */
#define ASTRIDE 516  /* smem A row stride (mod 32 == 4 -> conflict-free frags) */
#define WSTRIDE 72   /* smem W row stride (mod 32 == 8 -> conflict-free frags) */
#define LAYER_THREADS 512
#define LAYER_SMEM ((TM * ASTRIDE + 32 * WSTRIDE) * 4)

// ---------------- scratch (device globals; no allocation allowed) ----------
__device__ float g_hA[N_NODES * HID];
__device__ float g_hB[N_NODES * HID];
__device__ float g_R[N_NODES * HID];              // relu(agg)
__device__ float g_D[(size_t)N_EDGES * EMB];      // directions, ORIGINAL edge order
__device__ int2  g_se[N_EDGES];                   // CSR-ordered {src, edge_id}
__device__ int   g_rowptr[N_NODES + 1];
__device__ int   g_cnt[N_NODES];
__device__ int   g_cur[N_NODES];
__device__ float g_sums[HID];
__device__ float g_sumsq[HID];
__device__ float g_pooled[N_GRAPHS * HID];
__device__ int   g_done;

// ---------------- tf32 helpers ---------------------------------------------
__device__ __forceinline__ unsigned tf32cvt(float x) {
    unsigned r;
    asm("cvt.rna.tf32.f32 %0, %1;" : "=r"(r) : "f"(x));
    return r;
}
__device__ __forceinline__ void mma_tf32(float* c,
                                         unsigned a0, unsigned a1, unsigned a2, unsigned a3,
                                         unsigned b0, unsigned b1) {
    asm volatile(
        "mma.sync.aligned.m16n8k8.row.col.f32.tf32.tf32.f32 "
        "{%0,%1,%2,%3}, {%4,%5,%6,%7}, {%8,%9}, {%0,%1,%2,%3};"
        : "+f"(c[0]), "+f"(c[1]), "+f"(c[2]), "+f"(c[3])
        : "r"(a0), "r"(a1), "r"(a2), "r"(a3), "r"(b0), "r"(b1));
}

// ---------------- CSR build ------------------------------------------------
__global__ void k_zero_cc() {
    int i = blockIdx.x * blockDim.x + threadIdx.x;
    if (i < N_NODES) { g_cnt[i] = 0; g_cur[i] = 0; }
    if (blockIdx.x == 0) {
        int t = threadIdx.x;
        if (t < HID) { g_sums[t] = 0.f; g_sumsq[t] = 0.f; }
        if (t == 0) g_done = 0;
        for (int j = t; j < N_GRAPHS * HID; j += blockDim.x) g_pooled[j] = 0.f;
    }
}

// histogram of dst + per-edge normalized direction (coalesced write, edge order)
__global__ void k_hist_dir(const int* __restrict__ src, const int* __restrict__ dst,
                           const float* __restrict__ c) {
    int e = blockIdx.x * blockDim.x + threadIdx.x;
    if (e >= N_EDGES) return;
    int s = src[e], t = dst[e];
    atomicAdd(&g_cnt[t], 1);
    float4 s0 = __ldg((const float4*)&c[s * EMB]);
    float4 s1 = __ldg((const float4*)&c[s * EMB + 4]);
    float4 t0 = __ldg((const float4*)&c[t * EMB]);
    float4 t1 = __ldg((const float4*)&c[t * EMB + 4]);
    float4 d0 = make_float4(s0.x - t0.x, s0.y - t0.y, s0.z - t0.z, s0.w - t0.w);
    float4 d1 = make_float4(s1.x - t1.x, s1.y - t1.y, s1.z - t1.z, s1.w - t1.w);
    float nn = d0.x * d0.x + d0.y * d0.y + d0.z * d0.z + d0.w * d0.w
             + d1.x * d1.x + d1.y * d1.y + d1.z * d1.z + d1.w * d1.w;
    float sc = 1.0f / fmaxf(sqrtf(nn), 1e-12f);
    d0.x *= sc; d0.y *= sc; d0.z *= sc; d0.w *= sc;
    d1.x *= sc; d1.y *= sc; d1.z *= sc; d1.w *= sc;
    *(float4*)&g_D[(size_t)e * EMB]     = d0;
    *(float4*)&g_D[(size_t)e * EMB + 4] = d1;
}

// single-block scan: 1024 threads x 25 contiguous counts each
__global__ void k_scan() {
    const int PER = 25;
    __shared__ int wsum[32];
    int tid = threadIdx.x, lane = tid & 31, wid = tid >> 5;
    int base = tid * PER;
    int v[PER];
    int s = 0;
    #pragma unroll
    for (int j = 0; j < PER; j++) {
        int i = base + j;
        int cv = (i < N_NODES) ? g_cnt[i] : 0;
        v[j] = s;
        s += cv;
    }
    int x = s;
    #pragma unroll
    for (int o = 1; o < 32; o <<= 1) {
        int t = __shfl_up_sync(0xffffffffu, x, o);
        if (lane >= o) x += t;
    }
    if (lane == 31) wsum[wid] = x;
    __syncthreads();
    if (wid == 0) {
        int w = wsum[lane];
        #pragma unroll
        for (int o = 1; o < 32; o <<= 1) {
            int t = __shfl_up_sync(0xffffffffu, w, o);
            if (lane >= o) w += t;
        }
        wsum[lane] = w;
    }
    __syncthreads();
    int off = x - s + (wid > 0 ? wsum[wid - 1] : 0);
    #pragma unroll
    for (int j = 0; j < PER; j++) {
        int i = base + j;
        if (i <= N_NODES) g_rowptr[i] = off + v[j];
    }
}

// scatter edge -> CSR slot; only 8 bytes scattered per edge
__global__ void k_scatter(const int* __restrict__ src, const int* __restrict__ dst) {
    int e = blockIdx.x * blockDim.x + threadIdx.x;
    if (e >= N_EDGES) return;
    int s = src[e], t = dst[e];
    int p = g_rowptr[t] + atomicAdd(&g_cur[t], 1);
    g_se[p] = make_int2(s, e);
}

// ======== FUSED layer kernel: edge-agg (-> smem) + tf32 GEMM + BN stats =====
// Block: 512 threads (16 warps), 32-node tile.
// Phase 1: warp w aggregates nodes rowBase+2w, rowBase+2w+1; lane owns h-cols
//          {2*lane, 2*lane+1} (one LDG.64 per edge); tf32 rows -> smem A.
// Phase 2: W tiles streamed with register prefetch; warp w = (rg=w>>3, wn=w&7)
//          computes rows rg*16..+15 x cols wn*8..+7.
__global__ void __launch_bounds__(LAYER_THREADS)
k_layer(const float* __restrict__ feat, int hsel, const float* __restrict__ W) {
    extern __shared__ unsigned smem_u[];
    unsigned* As = smem_u;                    // TM * ASTRIDE
    unsigned* Ws = smem_u + TM * ASTRIDE;     // 32 * WSTRIDE
    const float* __restrict__ h = (hsel == 0) ? feat : ((hsel == 1) ? g_hA : g_hB);
    int tid = threadIdx.x;
    int lane = tid & 31, w = tid >> 5;
    int rowBase = blockIdx.x * TM;

    // prefetch W tile 0 into registers before gather (latency fully hidden)
    int wk = tid >> 4, wq = tid & 15;
    float4 wreg = __ldg((const float4*)&W[wk * HID + wq * 4]);

    // ---- phase 1: aggregation (warp w -> tile rows 2w, 2w+1) ----
    #pragma unroll
    for (int q = 0; q < 2; q++) {
        int r = w * 2 + q;
        int node = rowBase + r;
        float a0[EMB], a1[EMB];   // a0: col 2*lane, a1: col 2*lane+1
        #pragma unroll
        for (int i = 0; i < EMB; i++) { a0[i] = 0.f; a1[i] = 0.f; }
        if (node < N_NODES) {
            int e0 = g_rowptr[node], e1 = g_rowptr[node + 1];
            #pragma unroll 4
            for (int e = e0; e < e1; e++) {
                int2 se = __ldg(&g_se[e]);
                float4 d0 = __ldg((const float4*)&g_D[(size_t)se.y * EMB]);
                float4 d1 = __ldg((const float4*)&g_D[(size_t)se.y * EMB + 4]);
                float2 hv = __ldg((const float2*)&h[se.x * HID + 2 * lane]);
                float h0 = hv.x, h1 = hv.y;
                a0[0] += d0.x * h0;  a1[0] += d0.x * h1;
                a0[1] += d0.y * h0;  a1[1] += d0.y * h1;
                a0[2] += d0.z * h0;  a1[2] += d0.z * h1;
                a0[3] += d0.w * h0;  a1[3] += d0.w * h1;
                a0[4] += d1.x * h0;  a1[4] += d1.x * h1;
                a0[5] += d1.y * h0;  a1[5] += d1.y * h1;
                a0[6] += d1.z * h0;  a1[6] += d1.z * h1;
                a0[7] += d1.w * h0;  a1[7] += d1.w * h1;
            }
        }
        #pragma unroll
        for (int i = 0; i < EMB; i++) {
            // storage offset == k-index (i*64 + 2*lane), one STS.64 per emb-row
            *(uint2*)&As[r * ASTRIDE + i * HID + 2 * lane] =
                make_uint2(tf32cvt(a0[i]), tf32cvt(a1[i]));
        }
    }
    __syncthreads();

    // ---- phase 2: GEMM (32 x 64 x 512), reg-prefetched W tiles ----
    int g = lane >> 2, tig = lane & 3;
    int rg = w >> 3, wn = w & 7;
    int arow0 = (rg * 16 + g) * ASTRIDE;
    int arow1 = (rg * 16 + g + 8) * ASTRIDE;
    float acc[4] = {0.f, 0.f, 0.f, 0.f};
    for (int kb = 0; kb < KDIM; kb += 32) {
        Ws[wk * WSTRIDE + wq * 4]     = tf32cvt(wreg.x);
        Ws[wk * WSTRIDE + wq * 4 + 1] = tf32cvt(wreg.y);
        Ws[wk * WSTRIDE + wq * 4 + 2] = tf32cvt(wreg.z);
        Ws[wk * WSTRIDE + wq * 4 + 3] = tf32cvt(wreg.w);
        __syncthreads();
        if (kb + 32 < KDIM)
            wreg = __ldg((const float4*)&W[(kb + 32 + wk) * HID + wq * 4]);
        #pragma unroll
        for (int kk = 0; kk < 4; kk++) {
            int kc = kb + kk * 8;
            unsigned a0 = As[arow0 + kc + tig];
            unsigned a1 = As[arow1 + kc + tig];
            unsigned a2 = As[arow0 + kc + tig + 4];
            unsigned a3 = As[arow1 + kc + tig + 4];
            unsigned b0 = Ws[(kk * 8 + tig) * WSTRIDE + wn * 8 + g];
            unsigned b1 = Ws[(kk * 8 + tig + 4) * WSTRIDE + wn * 8 + g];
            mma_tf32(acc, a0, a1, a2, a3, b0, b1);
        }
        __syncthreads();
    }

    // ---- epilogue: relu + store + column stats ----
    int r0 = rowBase + rg * 16 + g, r1 = r0 + 8;
    int col = wn * 8 + tig * 2;
    float v0 = fmaxf(acc[0], 0.f), v1 = fmaxf(acc[1], 0.f);
    float v2 = fmaxf(acc[2], 0.f), v3 = fmaxf(acc[3], 0.f);
    if (r0 < N_NODES) *(float2*)&g_R[r0 * HID + col] = make_float2(v0, v1);
    if (r1 < N_NODES) *(float2*)&g_R[r1 * HID + col] = make_float2(v2, v3);
    float cS0 = v0 + v2, cS1 = v1 + v3;
    float cQ0 = v0 * v0 + v2 * v2, cQ1 = v1 * v1 + v3 * v3;
    #pragma unroll
    for (int o = 16; o >= 4; o >>= 1) {
        cS0 += __shfl_xor_sync(0xffffffffu, cS0, o);
        cS1 += __shfl_xor_sync(0xffffffffu, cS1, o);
        cQ0 += __shfl_xor_sync(0xffffffffu, cQ0, o);
        cQ1 += __shfl_xor_sync(0xffffffffu, cQ1, o);
    }
    if (g == 0) {
        atomicAdd(&g_sums[col], cS0);
        atomicAdd(&g_sums[col + 1], cS1);
        atomicAdd(&g_sumsq[col], cQ0);
        atomicAdd(&g_sumsq[col + 1], cQ1);
    }
}

// ------- BN normalize + shortcut + pooling + (last block) classifier -------
// Last block also re-zeros g_sums/g_sumsq/g_pooled/g_done for the next layer.
__global__ void k_norm_pool(const float* __restrict__ feat, int hinsel, int houtsel,
                            const float* __restrict__ gamma, const float* __restrict__ beta,
                            const int* __restrict__ gids, int shortcut,
                            const float* __restrict__ cW1, const float* __restrict__ cb1,
                            const float* __restrict__ cg1, const float* __restrict__ cbt1,
                            const float* __restrict__ cW2, const float* __restrict__ cb2,
                            float* __restrict__ out, int accumulate) {
    const float* __restrict__ hin = (hinsel == 0) ? feat : ((hinsel == 1) ? g_hA : g_hB);
    float* hout = (houtsel == 1) ? g_hA : g_hB;
    int tid = threadIdx.x;        // 512 -> 8 nodes x 64 cols per block
    int k = tid & 63, nl = tid >> 6;
    int n = blockIdx.x * 8 + nl;  // 3125*8 == 25000 exactly

    __shared__ float ps[N_GRAPHS * HID];
    for (int i = tid; i < N_GRAPHS * HID; i += 512) ps[i] = 0.f;
    __syncthreads();

    const float inv = 1.0f / (float)N_NODES;
    float mu = g_sums[k] * inv;
    float var = g_sumsq[k] * inv - mu * mu;
    float rstd = rsqrtf(var + 1e-5f);
    float v = gamma[k] * (g_R[n * HID + k] - mu) * rstd + beta[k];
    if (shortcut) v += hin[n * HID + k];
    hout[n * HID + k] = v;

    int g = gids[n];
    atomicAdd(&ps[g * HID + k], v);
    __syncthreads();

    int gmin = gids[blockIdx.x * 8];
    int gmax = gids[blockIdx.x * 8 + 7];
    int span = (gmax - gmin + 1) * HID;
    for (int i = tid; i < span; i += 512)
        atomicAdd(&g_pooled[gmin * HID + i], ps[gmin * HID + i]);

    // ---- last-block classifier + state reset ----
    __shared__ int s_last;
    __threadfence();
    __syncthreads();
    if (tid == 0) s_last = (atomicAdd(&g_done, 1) == (int)gridDim.x - 1) ? 1 : 0;
    __syncthreads();
    if (!s_last) return;

    __shared__ float xp[N_GRAPHS * HID];
    __shared__ float y[N_GRAPHS * 32];
    __shared__ float mus[32], rss[32];
    for (int i = tid; i < N_GRAPHS * HID; i += 512) {
        xp[i] = g_pooled[i];
        g_pooled[i] = 0.f;                 // reset for next layer
    }
    if (tid < HID) { g_sums[tid] = 0.f; g_sumsq[tid] = 0.f; }
    if (tid == 0) g_done = 0;
    __syncthreads();
    {
        int r = tid >> 5, c = tid & 31;
        float acc = cb1[c];
        #pragma unroll 8
        for (int j = 0; j < HID; j++) acc += xp[r * HID + j] * cW1[j * 32 + c];
        y[r * 32 + c] = acc;
    }
    __syncthreads();
    if (tid < 32) {
        float s = 0.f, s2 = 0.f;
        #pragma unroll
        for (int r = 0; r < N_GRAPHS; r++) {
            float vv = y[r * 32 + tid];
            s += vv; s2 += vv * vv;
        }
        float m = s / (float)N_GRAPHS;
        float vr = s2 / (float)N_GRAPHS - m * m;
        mus[tid] = m;
        rss[tid] = rsqrtf(vr + 1e-5f);
    }
    __syncthreads();
    {
        int r = tid >> 5, c = tid & 31;
        float vv = cg1[c] * (y[r * 32 + c] - mus[c]) * rss[c] + cbt1[c];
        y[r * 32 + c] = fmaxf(vv, 0.f);
    }
    __syncthreads();
    if (tid < N_GRAPHS * N_CLASSES) {
        int r = tid / N_CLASSES, c = tid % N_CLASSES;
        float acc = cb2[c];
        #pragma unroll
        for (int j = 0; j < 32; j++) acc += y[r * 32 + j] * cW2[j * N_CLASSES + c];
        if (accumulate) out[r * N_CLASSES + c] += acc;
        else            out[r * N_CLASSES + c] = acc;
    }
}

// ---------------- launcher -------------------------------------------------
extern "C" void kernel_launch(void* const* d_in, const int* in_sizes, int n_in,
                              void* d_out, int out_size) {
    const float* feature = (const float*)d_in[0];
    const float* spemb   = (const float*)d_in[1];
    const int*   src     = (const int*)d_in[2];
    const int*   dst     = (const int*)d_in[3];
    const int*   gids    = (const int*)d_in[4];
    const float* W[3]  = { (const float*)d_in[5], (const float*)d_in[6], (const float*)d_in[7] };
    const float* gm[3] = { (const float*)d_in[8], (const float*)d_in[10], (const float*)d_in[12] };
    const float* bt[3] = { (const float*)d_in[9], (const float*)d_in[11], (const float*)d_in[13] };
    const float* cW1  = (const float*)d_in[14];
    const float* cb1  = (const float*)d_in[15];
    const float* cg1  = (const float*)d_in[16];
    const float* cbt1 = (const float*)d_in[17];
    const float* cW2  = (const float*)d_in[18];
    const float* cb2  = (const float*)d_in[19];
    float* out = (float*)d_out;

    static int smem_set = 0;
    if (!smem_set) {
        cudaFuncSetAttribute(k_layer, cudaFuncAttributeMaxDynamicSharedMemorySize,
                             LAYER_SMEM);
        smem_set = 1;
    }

    k_zero_cc<<<(N_NODES + 255) / 256, 256>>>();
    k_hist_dir<<<(N_EDGES + 255) / 256, 256>>>(src, dst, spemb);
    k_scan<<<1, 1024>>>();
    k_scatter<<<(N_EDGES + 255) / 256, 256>>>(src, dst);

    int hin = 0, hout = 1;
    for (int L = 0; L < 3; L++) {
        k_layer<<<(N_NODES + TM - 1) / TM, LAYER_THREADS, LAYER_SMEM>>>(feature, hin, W[L]);
        k_norm_pool<<<N_NODES / 8, 512>>>(feature, hin, hout, gm[L], bt[L], gids,
                                          L > 0 ? 1 : 0,
                                          cW1, cb1, cg1, cbt1, cW2, cb2,
                                          out, L > 0 ? 1 : 0);
        hin = hout;
        hout = (hout == 1) ? 2 : 1;
    }
}